// round 5
// baseline (speedup 1.0000x reference)
#include <cuda_runtime.h>
#include <cuda_bf16.h>

#define BATCH 64
#define NPTS  32768
#define NQ    256
#define DD    256
#define FPS_T 512            // threads per FPS CTA
#define PPT   (NPTS / FPS_T) // 64 points per thread

// ---------------- device scratch (static, no runtime alloc) ----------------
__device__ float g_x[BATCH * NPTS];
__device__ float g_y[BATCH * NPTS];
__device__ float g_z[BATCH * NPTS];
__device__ int   g_inds[BATCH * NQ];
__device__ float g_pos[BATCH * NQ * DD];   // [b][n][d]
__device__ float g_h[BATCH * NQ * DD];     // [b][n][d]

// ---------------- 1) AoS -> SoA transpose (float4, coalesced) --------------
// Each thread handles 4 points = 12 floats = 3 float4 loads.
__global__ void k_transpose(const float* __restrict__ xyz) {
    const int q = blockIdx.x * blockDim.x + threadIdx.x;   // 4-point group id
    if (q >= (BATCH * NPTS) / 4) return;
    const float4* src = reinterpret_cast<const float4*>(xyz) + 3 * q;
    const float4 v0 = src[0];   // x0 y0 z0 x1
    const float4 v1 = src[1];   // y1 z1 x2 y2
    const float4 v2 = src[2];   // z2 x3 y3 z3
    float4* ox = reinterpret_cast<float4*>(g_x) + q;
    float4* oy = reinterpret_cast<float4*>(g_y) + q;
    float4* oz = reinterpret_cast<float4*>(g_z) + q;
    *ox = make_float4(v0.x, v0.w, v1.z, v2.y);
    *oy = make_float4(v0.y, v1.x, v1.w, v2.z);
    *oz = make_float4(v0.z, v1.y, v2.x, v2.w);
}

// ---------------- 2) Furthest point sampling ----------------
// One CTA per batch, 512 threads, dist in registers (64/thread; 128-reg
// budget at 512 thr -> no spills). Matches jax reference:
//   inds[0]=0; for it in 1..255:
//     dist = min(dist, ||p - xyz[inds[it-1]]||^2); inds[it] = argmax (first max)
// Distance uses XLA-style FMA contraction: d = fma(dz,dz, fma(dy,dy, dx*dx))
__global__ __launch_bounds__(FPS_T, 1) void k_fps() {
    const int b = blockIdx.x;
    const int t = threadIdx.x;
    const float* __restrict__ X = g_x + b * NPTS;
    const float* __restrict__ Y = g_y + b * NPTS;
    const float* __restrict__ Z = g_z + b * NPTS;

    __shared__ float sC[3];
    __shared__ float sV[16];
    __shared__ int   sI[16];

    float dist[PPT];
#pragma unroll
    for (int i = 0; i < PPT; i++) dist[i] = 1e10f;

    if (t == 0) {
        sC[0] = X[0]; sC[1] = Y[0]; sC[2] = Z[0];
        g_inds[b * NQ] = 0;
    }
    __syncthreads();

    const int lane = t & 31;
    const int wid  = t >> 5;            // 0..15

    for (int it = 1; it < NQ; ++it) {
        const float cx = sC[0], cy = sC[1], cz = sC[2];
        float lmax = -1.0f;
        int   lidx = 0;

#pragma unroll
        for (int c = 0; c < PPT / 4; ++c) {             // 16 float4 groups
            const int e = c * (FPS_T * 4) + 4 * t;      // element index within batch
            const float4 xs = *reinterpret_cast<const float4*>(X + e);
            const float4 ys = *reinterpret_cast<const float4*>(Y + e);
            const float4 zs = *reinterpret_cast<const float4*>(Z + e);
            const float px[4] = {xs.x, xs.y, xs.z, xs.w};
            const float py[4] = {ys.x, ys.y, ys.z, ys.w};
            const float pz[4] = {zs.x, zs.y, zs.z, zs.w};
#pragma unroll
            for (int k = 0; k < 4; ++k) {
                const float dx = __fsub_rn(px[k], cx);
                const float dy = __fsub_rn(py[k], cy);
                const float dz = __fsub_rn(pz[k], cz);
                const float d  = __fmaf_rn(dz, dz,
                                  __fmaf_rn(dy, dy, __fmul_rn(dx, dx)));
                const int r = c * 4 + k;
                const float nd = fminf(dist[r], d);
                dist[r] = nd;
                if (nd > lmax) { lmax = nd; lidx = e + k; }  // strict > keeps lowest idx
            }
        }

        // warp-level argmax with lowest-index tie-break
#pragma unroll
        for (int off = 16; off > 0; off >>= 1) {
            const float ov = __shfl_down_sync(0xFFFFFFFFu, lmax, off);
            const int   oi = __shfl_down_sync(0xFFFFFFFFu, lidx, off);
            if (ov > lmax || (ov == lmax && oi < lidx)) { lmax = ov; lidx = oi; }
        }
        if (lane == 0) { sV[wid] = lmax; sI[wid] = lidx; }
        __syncthreads();

        if (t < 32) {
            lmax = (lane < 16) ? sV[lane] : -1.0f;
            lidx = (lane < 16) ? sI[lane] : 0x7FFFFFFF;
#pragma unroll
            for (int off = 8; off > 0; off >>= 1) {
                const float ov = __shfl_down_sync(0xFFFFFFFFu, lmax, off);
                const int   oi = __shfl_down_sync(0xFFFFFFFFu, lidx, off);
                if (ov > lmax || (ov == lmax && oi < lidx)) { lmax = ov; lidx = oi; }
            }
            if (lane == 0) {
                g_inds[b * NQ + it] = lidx;
                sC[0] = X[lidx]; sC[1] = Y[lidx]; sC[2] = Z[lidx];
            }
        }
        __syncthreads();
    }
}

// ---------------- 3) gather + fourier positional embedding ----------------
__global__ __launch_bounds__(NQ) void k_embed(const float* __restrict__ xyz,
                                              const float* __restrict__ pc_min,
                                              const float* __restrict__ pc_max,
                                              const float* __restrict__ gB,
                                              float* __restrict__ out_xyz) {
    const int b = blockIdx.x;
    const int n = threadIdx.x;

    __shared__ float sG[3 * 128];   // gauss_B row-major [3][128]
    for (int i = n; i < 3 * 128; i += NQ) sG[i] = gB[i];
    __syncthreads();

    const int idx = g_inds[b * NQ + n];
    const float* p = xyz + ((long)b * NPTS + idx) * 3;
    const float qx = p[0], qy = p[1], qz = p[2];

    float* oq = out_xyz + ((long)b * NQ + n) * 3;
    oq[0] = qx; oq[1] = qy; oq[2] = qz;

    const float mn0 = pc_min[b * 3 + 0], mn1 = pc_min[b * 3 + 1], mn2 = pc_min[b * 3 + 2];
    const float mx0 = pc_max[b * 3 + 0], mx1 = pc_max[b * 3 + 1], mx2 = pc_max[b * 3 + 2];
    const float n0 = (qx - mn0) / (mx0 - mn0);
    const float n1 = (qy - mn1) / (mx1 - mn1);
    const float n2 = (qz - mn2) / (mx2 - mn2);

    float* pp = g_pos + ((long)b * NQ + n) * DD;
    const float TWO_PI = 6.2831853071795864769f;
#pragma unroll 4
    for (int f = 0; f < 128; ++f) {
        const float pr = TWO_PI * (n0 * sG[f] + n1 * sG[128 + f] + n2 * sG[256 + f]);
        float s, c;
        sincosf(pr, &s, &c);
        pp[f]       = s;
        pp[128 + f] = c;
    }
}

// ---------------- 4) batched SGEMM: C[m][n] = relu(sum_k A[m][k]*B[n][k]+bias)
// 128x128 tile, BK=8, 256 threads, 8x8 microtile.
// bias_mode 0: bias[n] (col), 1: bias[m] (row)
__device__ __forceinline__ void gemm_body(const float* __restrict__ A,
                                          const float* __restrict__ B,
                                          const float* __restrict__ bias,
                                          float* __restrict__ C,
                                          int bias_mode) {
    __shared__ float As[8][128];
    __shared__ float Bs[8][128];

    const int tid = threadIdx.x;      // 0..255
    const int tx = tid & 15;
    const int ty = tid >> 4;
    const int m0 = blockIdx.y * 128;
    const int n0 = blockIdx.x * 128;
    const int lrow = tid >> 1;        // 0..127
    const int lk4  = (tid & 1) << 2;  // 0 or 4

    float acc[8][8] = {};

    for (int k0 = 0; k0 < 256; k0 += 8) {
        const float4 a  = *reinterpret_cast<const float4*>(A + (m0 + lrow) * 256 + k0 + lk4);
        const float4 bq = *reinterpret_cast<const float4*>(B + (n0 + lrow) * 256 + k0 + lk4);
        As[lk4 + 0][lrow] = a.x;  As[lk4 + 1][lrow] = a.y;
        As[lk4 + 2][lrow] = a.z;  As[lk4 + 3][lrow] = a.w;
        Bs[lk4 + 0][lrow] = bq.x; Bs[lk4 + 1][lrow] = bq.y;
        Bs[lk4 + 2][lrow] = bq.z; Bs[lk4 + 3][lrow] = bq.w;
        __syncthreads();

#pragma unroll
        for (int k = 0; k < 8; ++k) {
            const float4 a0 = *reinterpret_cast<const float4*>(&As[k][(ty << 3) + 0]);
            const float4 a1 = *reinterpret_cast<const float4*>(&As[k][(ty << 3) + 4]);
            const float4 b0 = *reinterpret_cast<const float4*>(&Bs[k][(tx << 3) + 0]);
            const float4 b1 = *reinterpret_cast<const float4*>(&Bs[k][(tx << 3) + 4]);
            const float am[8] = {a0.x, a0.y, a0.z, a0.w, a1.x, a1.y, a1.z, a1.w};
            const float bn[8] = {b0.x, b0.y, b0.z, b0.w, b1.x, b1.y, b1.z, b1.w};
#pragma unroll
            for (int i = 0; i < 8; ++i)
#pragma unroll
                for (int j = 0; j < 8; ++j)
                    acc[i][j] += am[i] * bn[j];
        }
        __syncthreads();
    }

#pragma unroll
    for (int i = 0; i < 8; ++i) {
        const int m = m0 + (ty << 3) + i;
#pragma unroll
        for (int j = 0; j < 8; ++j) {
            const int n = n0 + (tx << 3) + j;
            const float v = acc[i][j] + bias[bias_mode ? m : n];
            C[m * 256 + n] = fmaxf(v, 0.0f);
        }
    }
}

// GEMM1: h[b][n][d] = relu( sum_c pos[b][n][c] * W1[d][c] + b1[d] )
__global__ __launch_bounds__(256) void k_gemm1(const float* __restrict__ W1,
                                               const float* __restrict__ b1) {
    const float* A = g_pos + (long)blockIdx.z * NQ * DD;  // [n][c]
    float*       C = g_h   + (long)blockIdx.z * NQ * DD;  // [n][d]
    gemm_body(A, W1, b1, C, 0);
}

// GEMM2: out[b][d][n] = relu( sum_c W2[d][c] * h[b][n][c] + b2[d] )
__global__ __launch_bounds__(256) void k_gemm2(const float* __restrict__ W2,
                                               const float* __restrict__ b2,
                                               float* __restrict__ outp) {
    const float* B = g_h + (long)blockIdx.z * NQ * DD;    // [n][c]
    float*       C = outp + (long)blockIdx.z * DD * NQ;   // [d][n]
    gemm_body(W2, B, b2, C, 1);
}

// ---------------- launch ----------------
extern "C" void kernel_launch(void* const* d_in, const int* in_sizes, int n_in,
                              void* d_out, int out_size) {
    const float* xyz    = (const float*)d_in[0];
    const float* pc_min = (const float*)d_in[1];
    const float* pc_max = (const float*)d_in[2];
    const float* gB     = (const float*)d_in[3];
    const float* W1     = (const float*)d_in[4];
    const float* b1     = (const float*)d_in[5];
    const float* W2     = (const float*)d_in[6];
    const float* b2     = (const float*)d_in[7];
    float* out = (float*)d_out;

    k_transpose<<<(BATCH * NPTS / 4 + 255) / 256, 256>>>(xyz);
    k_fps<<<BATCH, FPS_T>>>();
    k_embed<<<BATCH, NQ>>>(xyz, pc_min, pc_max, gB, out);
    dim3 gg(2, 2, BATCH);
    k_gemm1<<<gg, 256>>>(W1, b1);
    k_gemm2<<<gg, 256>>>(W2, b2, out + (long)BATCH * NQ * 3);
}

// round 10
// speedup vs baseline: 1.2967x; 1.2967x over previous
#include <cuda_runtime.h>
#include <cuda_bf16.h>

#define BATCH 64
#define NPTS  32768
#define NQ    256
#define DD    256
#define FPS_T 512                   // threads per FPS CTA
#define CSZ   2                     // cluster size (CTAs per batch)
#define PPT   (NPTS / (FPS_T * CSZ))  // 32 points per thread

// ---------------- device scratch (static, no runtime alloc) ----------------
__device__ float g_x[BATCH * NPTS];
__device__ float g_y[BATCH * NPTS];
__device__ float g_z[BATCH * NPTS];
__device__ int   g_inds[BATCH * NQ];
__device__ float g_pos[BATCH * NQ * DD];   // [b][n][d]
__device__ float g_h[BATCH * NQ * DD];     // [b][n][d]

// pack: higher distance wins; equal distance -> lower index wins (u64 max)
__device__ __forceinline__ unsigned long long fps_pack(float v, int idx) {
    return ((unsigned long long)__float_as_uint(v) << 32) |
           (unsigned)(0x7FFFFFFF - idx);
}
__device__ __forceinline__ int fps_idx(unsigned long long pk) {
    return 0x7FFFFFFF - (int)(pk & 0xFFFFFFFFu);
}

// ---------------- 1) AoS -> SoA transpose (float4, coalesced) --------------
__global__ void k_transpose(const float* __restrict__ xyz) {
    const int q = blockIdx.x * blockDim.x + threadIdx.x;   // 4-point group id
    if (q >= (BATCH * NPTS) / 4) return;
    const float4* src = reinterpret_cast<const float4*>(xyz) + 3 * q;
    const float4 v0 = src[0];   // x0 y0 z0 x1
    const float4 v1 = src[1];   // y1 z1 x2 y2
    const float4 v2 = src[2];   // z2 x3 y3 z3
    float4* ox = reinterpret_cast<float4*>(g_x) + q;
    float4* oy = reinterpret_cast<float4*>(g_y) + q;
    float4* oz = reinterpret_cast<float4*>(g_z) + q;
    *ox = make_float4(v0.x, v0.w, v1.z, v2.y);
    *oy = make_float4(v0.y, v1.x, v1.w, v2.z);
    *oz = make_float4(v0.z, v1.y, v2.x, v2.w);
}

// ---------------- 2) Furthest point sampling (cluster-2 per batch) ---------
// 2 CTAs per batch (cluster), 512 threads each, dist in regs (32/thread).
// Inner-loop arithmetic identical to the validated R5 kernel:
//   d = fma(dz,dz, fma(dy,dy, dx*dx)), first-max argmax semantics.
// Cross-CTA combine: packed u64 winner exchanged via DSMEM, one
// barrier.cluster per iteration; parity double-buffered slots.
__global__ __launch_bounds__(FPS_T, 1) __cluster_dims__(CSZ, 1, 1)
void k_fps() {
    const int cta  = blockIdx.x;
    const int b    = cta >> 1;
    const int rank = cta & 1;
    const int t    = threadIdx.x;
    const float* __restrict__ X = g_x + b * NPTS;   // full batch pointers
    const float* __restrict__ Y = g_y + b * NPTS;
    const float* __restrict__ Z = g_z + b * NPTS;

    __shared__ unsigned long long sW[16];
    __shared__ unsigned long long sSlot[2][CSZ];    // [parity][rank]

    float dist[PPT];
#pragma unroll
    for (int i = 0; i < PPT; i++) dist[i] = 1e10f;

    if (rank == 0 && t == 0) g_inds[b * NQ] = 0;

    // initial centroid: point 0 (broadcast load)
    float cx = X[0], cy = Y[0], cz = Z[0];

    const int lane = t & 31;
    const int wid  = t >> 5;            // 0..15
    const int base = rank * (NPTS / CSZ);

    for (int it = 1; it < NQ; ++it) {
        float lmax = -1.0f;
        int   lidx = 0;

#pragma unroll
        for (int c = 0; c < PPT / 4; ++c) {              // 8 float4 groups
            const int e = base + c * (FPS_T * 4) + 4 * t;
            const float4 xs = *reinterpret_cast<const float4*>(X + e);
            const float4 ys = *reinterpret_cast<const float4*>(Y + e);
            const float4 zs = *reinterpret_cast<const float4*>(Z + e);
            const float px[4] = {xs.x, xs.y, xs.z, xs.w};
            const float py[4] = {ys.x, ys.y, ys.z, ys.w};
            const float pz[4] = {zs.x, zs.y, zs.z, zs.w};
#pragma unroll
            for (int k = 0; k < 4; ++k) {
                const float dx = __fsub_rn(px[k], cx);
                const float dy = __fsub_rn(py[k], cy);
                const float dz = __fsub_rn(pz[k], cz);
                const float d  = __fmaf_rn(dz, dz,
                                  __fmaf_rn(dy, dy, __fmul_rn(dx, dx)));
                const int r = c * 4 + k;
                const float nd = fminf(dist[r], d);
                dist[r] = nd;
                if (nd > lmax) { lmax = nd; lidx = e + k; }  // strict > keeps lowest idx
            }
        }

        // warp reduce (u64 max encodes value-then-lowest-index)
        unsigned long long pk = fps_pack(lmax, lidx);
#pragma unroll
        for (int off = 16; off > 0; off >>= 1) {
            const unsigned long long o = __shfl_down_sync(0xFFFFFFFFu, pk, off);
            if (o > pk) pk = o;
        }
        if (lane == 0) sW[wid] = pk;
        __syncthreads();

        if (t < 32) {
            pk = (lane < 16) ? sW[lane] : 0ULL;
#pragma unroll
            for (int off = 8; off > 0; off >>= 1) {
                const unsigned long long o = __shfl_down_sync(0xFFFFFFFFu, pk, off);
                if (o > pk) pk = o;
            }
            if (lane == 0) {
                // publish CTA winner to both CTAs' slot[parity][rank]
                sSlot[it & 1][rank] = pk;
                unsigned int laddr = (unsigned int)__cvta_generic_to_shared(
                                         &sSlot[it & 1][rank]);
                unsigned int raddr;
                asm volatile("mapa.shared::cluster.u32 %0, %1, %2;"
                             : "=r"(raddr) : "r"(laddr), "r"(rank ^ 1));
                asm volatile("st.shared::cluster.b64 [%0], %1;"
                             :: "r"(raddr), "l"(pk) : "memory");
            }
        }

        // one cluster barrier: orders remote+local slot stores (release/acquire)
        asm volatile("barrier.cluster.arrive.aligned;" ::: "memory");
        asm volatile("barrier.cluster.wait.aligned;" ::: "memory");

        const unsigned long long w0 = sSlot[it & 1][0];
        const unsigned long long w1 = sSlot[it & 1][1];
        const int widx = fps_idx(w0 > w1 ? w0 : w1);

        if (rank == 0 && t == 0) g_inds[b * NQ + it] = widx;
        cx = X[widx]; cy = Y[widx]; cz = Z[widx];   // broadcast load
    }
}

// ---------------- 3) gather + fourier positional embedding ----------------
__global__ __launch_bounds__(NQ) void k_embed(const float* __restrict__ xyz,
                                              const float* __restrict__ pc_min,
                                              const float* __restrict__ pc_max,
                                              const float* __restrict__ gB,
                                              float* __restrict__ out_xyz) {
    const int b = blockIdx.x;
    const int n = threadIdx.x;

    __shared__ float sG[3 * 128];   // gauss_B row-major [3][128]
    for (int i = n; i < 3 * 128; i += NQ) sG[i] = gB[i];
    __syncthreads();

    const int idx = g_inds[b * NQ + n];
    const float* p = xyz + ((long)b * NPTS + idx) * 3;
    const float qx = p[0], qy = p[1], qz = p[2];

    float* oq = out_xyz + ((long)b * NQ + n) * 3;
    oq[0] = qx; oq[1] = qy; oq[2] = qz;

    const float mn0 = pc_min[b * 3 + 0], mn1 = pc_min[b * 3 + 1], mn2 = pc_min[b * 3 + 2];
    const float mx0 = pc_max[b * 3 + 0], mx1 = pc_max[b * 3 + 1], mx2 = pc_max[b * 3 + 2];
    const float n0 = (qx - mn0) / (mx0 - mn0);
    const float n1 = (qy - mn1) / (mx1 - mn1);
    const float n2 = (qz - mn2) / (mx2 - mn2);

    float* pp = g_pos + ((long)b * NQ + n) * DD;
    const float TWO_PI = 6.2831853071795864769f;
#pragma unroll 4
    for (int f = 0; f < 128; ++f) {
        const float pr = TWO_PI * (n0 * sG[f] + n1 * sG[128 + f] + n2 * sG[256 + f]);
        float s, c;
        sincosf(pr, &s, &c);
        pp[f]       = s;
        pp[128 + f] = c;
    }
}

// ---------------- 4) batched SGEMM: C[m][n] = relu(sum_k A[m][k]*B[n][k]+bias)
// 128x128 tile, BK=8, 256 threads, 8x8 microtile.
// bias_mode 0: bias[n] (col), 1: bias[m] (row)
__device__ __forceinline__ void gemm_body(const float* __restrict__ A,
                                          const float* __restrict__ B,
                                          const float* __restrict__ bias,
                                          float* __restrict__ C,
                                          int bias_mode) {
    __shared__ float As[8][128];
    __shared__ float Bs[8][128];

    const int tid = threadIdx.x;      // 0..255
    const int tx = tid & 15;
    const int ty = tid >> 4;
    const int m0 = blockIdx.y * 128;
    const int n0 = blockIdx.x * 128;
    const int lrow = tid >> 1;        // 0..127
    const int lk4  = (tid & 1) << 2;  // 0 or 4

    float acc[8][8] = {};

    for (int k0 = 0; k0 < 256; k0 += 8) {
        const float4 a  = *reinterpret_cast<const float4*>(A + (m0 + lrow) * 256 + k0 + lk4);
        const float4 bq = *reinterpret_cast<const float4*>(B + (n0 + lrow) * 256 + k0 + lk4);
        As[lk4 + 0][lrow] = a.x;  As[lk4 + 1][lrow] = a.y;
        As[lk4 + 2][lrow] = a.z;  As[lk4 + 3][lrow] = a.w;
        Bs[lk4 + 0][lrow] = bq.x; Bs[lk4 + 1][lrow] = bq.y;
        Bs[lk4 + 2][lrow] = bq.z; Bs[lk4 + 3][lrow] = bq.w;
        __syncthreads();

#pragma unroll
        for (int k = 0; k < 8; ++k) {
            const float4 a0 = *reinterpret_cast<const float4*>(&As[k][(ty << 3) + 0]);
            const float4 a1 = *reinterpret_cast<const float4*>(&As[k][(ty << 3) + 4]);
            const float4 b0 = *reinterpret_cast<const float4*>(&Bs[k][(tx << 3) + 0]);
            const float4 b1 = *reinterpret_cast<const float4*>(&Bs[k][(tx << 3) + 4]);
            const float am[8] = {a0.x, a0.y, a0.z, a0.w, a1.x, a1.y, a1.z, a1.w};
            const float bn[8] = {b0.x, b0.y, b0.z, b0.w, b1.x, b1.y, b1.z, b1.w};
#pragma unroll
            for (int i = 0; i < 8; ++i)
#pragma unroll
                for (int j = 0; j < 8; ++j)
                    acc[i][j] += am[i] * bn[j];
        }
        __syncthreads();
    }

#pragma unroll
    for (int i = 0; i < 8; ++i) {
        const int m = m0 + (ty << 3) + i;
#pragma unroll
        for (int j = 0; j < 8; ++j) {
            const int n = n0 + (tx << 3) + j;
            const float v = acc[i][j] + bias[bias_mode ? m : n];
            C[m * 256 + n] = fmaxf(v, 0.0f);
        }
    }
}

// GEMM1: h[b][n][d] = relu( sum_c pos[b][n][c] * W1[d][c] + b1[d] )
__global__ __launch_bounds__(256) void k_gemm1(const float* __restrict__ W1,
                                               const float* __restrict__ b1) {
    const float* A = g_pos + (long)blockIdx.z * NQ * DD;  // [n][c]
    float*       C = g_h   + (long)blockIdx.z * NQ * DD;  // [n][d]
    gemm_body(A, W1, b1, C, 0);
}

// GEMM2: out[b][d][n] = relu( sum_c W2[d][c] * h[b][n][c] + b2[d] )
__global__ __launch_bounds__(256) void k_gemm2(const float* __restrict__ W2,
                                               const float* __restrict__ b2,
                                               float* __restrict__ outp) {
    const float* B = g_h + (long)blockIdx.z * NQ * DD;    // [n][c]
    float*       C = outp + (long)blockIdx.z * DD * NQ;   // [d][n]
    gemm_body(W2, B, b2, C, 1);
}

// ---------------- launch ----------------
extern "C" void kernel_launch(void* const* d_in, const int* in_sizes, int n_in,
                              void* d_out, int out_size) {
    const float* xyz    = (const float*)d_in[0];
    const float* pc_min = (const float*)d_in[1];
    const float* pc_max = (const float*)d_in[2];
    const float* gB     = (const float*)d_in[3];
    const float* W1     = (const float*)d_in[4];
    const float* b1     = (const float*)d_in[5];
    const float* W2     = (const float*)d_in[6];
    const float* b2     = (const float*)d_in[7];
    float* out = (float*)d_out;

    k_transpose<<<(BATCH * NPTS / 4 + 255) / 256, 256>>>(xyz);
    k_fps<<<BATCH * CSZ, FPS_T>>>();
    k_embed<<<BATCH, NQ>>>(xyz, pc_min, pc_max, gB, out);
    dim3 gg(2, 2, BATCH);
    k_gemm1<<<gg, 256>>>(W1, b1);
    k_gemm2<<<gg, 256>>>(W2, b2, out + (long)BATCH * NQ * 3);
}

// round 12
// speedup vs baseline: 1.7146x; 1.3223x over previous
#include <cuda_runtime.h>
#include <cuda_bf16.h>

#define BATCH 64
#define NPTS  32768
#define NQ    256
#define DD    256
#define FPS_T 512                   // threads per FPS CTA
#define CSZ   2                     // cluster size (CTAs per batch)
#define PPT   (NPTS / (FPS_T * CSZ))  // 32 points per thread
#define NGRP  (PPT / 4)             // 8 float4 groups per thread

// ---------------- device scratch (static, no runtime alloc) ----------------
__device__ float g_x[BATCH * NPTS];
__device__ float g_y[BATCH * NPTS];
__device__ float g_z[BATCH * NPTS];
__device__ int   g_inds[BATCH * NQ];
__device__ float g_pos[BATCH * NQ * DD];   // [b][n][d]
__device__ float g_h[BATCH * NQ * DD];     // [b][n][d]

// pack: [dist_bits:32 | it:8 (bits16..23) | (0x7FFF-idx):15]
// within one iteration (equal tag bits) u64 max == (max dist, tie -> min idx)
__device__ __forceinline__ unsigned long long fps_pack(float v, int idx, int it) {
    return ((unsigned long long)__float_as_uint(v) << 32) |
           ((unsigned)it << 16) | (unsigned)(0x7FFF - idx);
}
__device__ __forceinline__ int fps_idx(unsigned long long pk) {
    return 0x7FFF - (int)(pk & 0x7FFFu);
}

// ---------------- 1) AoS -> SoA transpose (float4, coalesced) --------------
__global__ void k_transpose(const float* __restrict__ xyz) {
    const int q = blockIdx.x * blockDim.x + threadIdx.x;   // 4-point group id
    if (q >= (BATCH * NPTS) / 4) return;
    const float4* src = reinterpret_cast<const float4*>(xyz) + 3 * q;
    const float4 v0 = src[0];   // x0 y0 z0 x1
    const float4 v1 = src[1];   // y1 z1 x2 y2
    const float4 v2 = src[2];   // z2 x3 y3 z3
    float4* ox = reinterpret_cast<float4*>(g_x) + q;
    float4* oy = reinterpret_cast<float4*>(g_y) + q;
    float4* oz = reinterpret_cast<float4*>(g_z) + q;
    *ox = make_float4(v0.x, v0.w, v1.z, v2.y);
    *oy = make_float4(v0.y, v1.x, v1.w, v2.z);
    *oz = make_float4(v0.z, v1.y, v2.x, v2.w);
}

// ---------------- 2) Furthest point sampling (cluster-2, mailbox) ---------
// 2 CTAs per batch. Inner-loop arithmetic byte-identical to the validated
// kernel. Cross-CTA combine via tagged DSMEM mailbox (no cluster barrier in
// the loop): thread0 remote-stores its CTA winner into the peer's parity
// slot; all threads poll the local slot until the 8-bit iteration tag
// matches. Register ping-pong prefetch hides point-load latency behind
// compute and the exchange.
__global__ __launch_bounds__(FPS_T, 1) __cluster_dims__(CSZ, 1, 1)
void k_fps() {
    const int cta  = blockIdx.x;
    const int b    = cta >> 1;
    const int rank = cta & 1;
    const int t    = threadIdx.x;
    const float* __restrict__ X = g_x + b * NPTS;
    const float* __restrict__ Y = g_y + b * NPTS;
    const float* __restrict__ Z = g_z + b * NPTS;

    __shared__ unsigned long long sW[16];
    __shared__ unsigned long long sOwn[2];    // [parity] own CTA winner
    __shared__ unsigned long long sPeer[2];   // [parity] peer winner (remote-written)

    float dist[PPT];
#pragma unroll
    for (int i = 0; i < PPT; i++) dist[i] = 1e10f;

    if (t == 0) {
        sPeer[0] = 0ULL; sPeer[1] = 0ULL;     // tag 0 != any it in 1..255
        if (rank == 0) g_inds[b * NQ] = 0;
    }
    __syncthreads();
    // peers must not receive a mailbox store before sPeer is zeroed
    asm volatile("barrier.cluster.arrive.aligned;" ::: "memory");
    asm volatile("barrier.cluster.wait.aligned;" ::: "memory");

    float cx = X[0], cy = Y[0], cz = Z[0];    // initial centroid (broadcast)

    const int lane = t & 31;
    const int wid  = t >> 5;                  // 0..15
    const int base = rank * (NPTS / CSZ);
    const int e0   = base + 4 * t;            // group-0 element index

    // prefetch group 0 for the first iteration
    float4 PX = *reinterpret_cast<const float4*>(X + e0);
    float4 PY = *reinterpret_cast<const float4*>(Y + e0);
    float4 PZ = *reinterpret_cast<const float4*>(Z + e0);

    for (int it = 1; it < NQ; ++it) {
        float lmax = -1.0f;
        int   lidx = 0;

#pragma unroll
        for (int c = 0; c < NGRP; ++c) {
            const float4 xs = PX, ys = PY, zs = PZ;
            if (c < NGRP - 1) {               // prefetch next group
                const int en = base + (c + 1) * (FPS_T * 4) + 4 * t;
                PX = *reinterpret_cast<const float4*>(X + en);
                PY = *reinterpret_cast<const float4*>(Y + en);
                PZ = *reinterpret_cast<const float4*>(Z + en);
            }
            const int e = base + c * (FPS_T * 4) + 4 * t;
            const float px[4] = {xs.x, xs.y, xs.z, xs.w};
            const float py[4] = {ys.x, ys.y, ys.z, ys.w};
            const float pz[4] = {zs.x, zs.y, zs.z, zs.w};
#pragma unroll
            for (int k = 0; k < 4; ++k) {
                const float dx = __fsub_rn(px[k], cx);
                const float dy = __fsub_rn(py[k], cy);
                const float dz = __fsub_rn(pz[k], cz);
                const float d  = __fmaf_rn(dz, dz,
                                  __fmaf_rn(dy, dy, __fmul_rn(dx, dx)));
                const int r = c * 4 + k;
                const float nd = fminf(dist[r], d);
                dist[r] = nd;
                if (nd > lmax) { lmax = nd; lidx = e + k; }  // strict > keeps lowest idx
            }
        }

        // prefetch group 0 for the NEXT iteration (addresses are
        // centroid-independent; latency hides behind reduce + exchange)
        PX = *reinterpret_cast<const float4*>(X + e0);
        PY = *reinterpret_cast<const float4*>(Y + e0);
        PZ = *reinterpret_cast<const float4*>(Z + e0);

        // warp reduce (u64 max = value-then-lowest-index, tags equal)
        unsigned long long pk = fps_pack(lmax, lidx, it);
#pragma unroll
        for (int off = 16; off > 0; off >>= 1) {
            const unsigned long long o = __shfl_down_sync(0xFFFFFFFFu, pk, off);
            if (o > pk) pk = o;
        }
        if (lane == 0) sW[wid] = pk;
        __syncthreads();

        if (t < 32) {
            pk = (lane < 16) ? sW[lane] : 0ULL;
#pragma unroll
            for (int off = 8; off > 0; off >>= 1) {
                const unsigned long long o = __shfl_down_sync(0xFFFFFFFFu, pk, off);
                if (o > pk) pk = o;
            }
            if (lane == 0) {
                sOwn[it & 1] = pk;
                // remote store into peer's sPeer[it&1] (single atomic 8B store)
                unsigned int laddr = (unsigned int)__cvta_generic_to_shared(
                                         &sPeer[it & 1]);
                unsigned int raddr;
                asm volatile("mapa.shared::cluster.u32 %0, %1, %2;"
                             : "=r"(raddr) : "r"(laddr), "r"(rank ^ 1));
                asm volatile("st.shared::cluster.b64 [%0], %1;"
                             :: "r"(raddr), "l"(pk) : "memory");
            }
        }
        __syncthreads();                       // publish sOwn locally

        const unsigned long long own = sOwn[it & 1];
        const volatile unsigned long long* vp = &sPeer[it & 1];
        unsigned long long pv = *vp;
        while ((unsigned)((pv >> 16) & 0xFFu) != (unsigned)(it & 0xFF)) pv = *vp;

        const int widx = fps_idx(own > pv ? own : pv);
        if (rank == 0 && t == 0) g_inds[b * NQ + it] = widx;
        cx = X[widx]; cy = Y[widx]; cz = Z[widx];   // broadcast load
    }

    // keep smem alive until the peer's last mailbox store has landed
    asm volatile("barrier.cluster.arrive.aligned;" ::: "memory");
    asm volatile("barrier.cluster.wait.aligned;" ::: "memory");
}

// ---------------- 3) gather + fourier positional embedding ----------------
__global__ __launch_bounds__(NQ) void k_embed(const float* __restrict__ xyz,
                                              const float* __restrict__ pc_min,
                                              const float* __restrict__ pc_max,
                                              const float* __restrict__ gB,
                                              float* __restrict__ out_xyz) {
    const int b = blockIdx.x;
    const int n = threadIdx.x;

    __shared__ float sG[3 * 128];   // gauss_B row-major [3][128]
    for (int i = n; i < 3 * 128; i += NQ) sG[i] = gB[i];
    __syncthreads();

    const int idx = g_inds[b * NQ + n];
    const float* p = xyz + ((long)b * NPTS + idx) * 3;
    const float qx = p[0], qy = p[1], qz = p[2];

    float* oq = out_xyz + ((long)b * NQ + n) * 3;
    oq[0] = qx; oq[1] = qy; oq[2] = qz;

    const float mn0 = pc_min[b * 3 + 0], mn1 = pc_min[b * 3 + 1], mn2 = pc_min[b * 3 + 2];
    const float mx0 = pc_max[b * 3 + 0], mx1 = pc_max[b * 3 + 1], mx2 = pc_max[b * 3 + 2];
    const float n0 = (qx - mn0) / (mx0 - mn0);
    const float n1 = (qy - mn1) / (mx1 - mn1);
    const float n2 = (qz - mn2) / (mx2 - mn2);

    float* pp = g_pos + ((long)b * NQ + n) * DD;
    const float TWO_PI = 6.2831853071795864769f;
#pragma unroll 4
    for (int f = 0; f < 128; ++f) {
        const float pr = TWO_PI * (n0 * sG[f] + n1 * sG[128 + f] + n2 * sG[256 + f]);
        float s, c;
        sincosf(pr, &s, &c);
        pp[f]       = s;
        pp[128 + f] = c;
    }
}

// ---------------- 4) batched SGEMM: C[m][n] = relu(sum_k A[m][k]*B[n][k]+bias)
// 128x128 tile, BK=8, 256 threads, 8x8 microtile, double-buffered smem
// (one __syncthreads per k0 step; global loads overlap compute).
// bias_mode 0: bias[n] (col), 1: bias[m] (row)
__device__ __forceinline__ void gemm_body(const float* __restrict__ A,
                                          const float* __restrict__ B,
                                          const float* __restrict__ bias,
                                          float* __restrict__ C,
                                          int bias_mode) {
    __shared__ float As[2][8][128];
    __shared__ float Bs[2][8][128];

    const int tid = threadIdx.x;      // 0..255
    const int tx = tid & 15;
    const int ty = tid >> 4;
    const int m0 = blockIdx.y * 128;
    const int n0 = blockIdx.x * 128;
    const int lrow = tid >> 1;        // 0..127
    const int lk4  = (tid & 1) << 2;  // 0 or 4

    float acc[8][8] = {};

    // prologue: stage k0=0 into buffer 0
    {
        const float4 a  = *reinterpret_cast<const float4*>(A + (m0 + lrow) * 256 + lk4);
        const float4 bq = *reinterpret_cast<const float4*>(B + (n0 + lrow) * 256 + lk4);
        As[0][lk4 + 0][lrow] = a.x;  As[0][lk4 + 1][lrow] = a.y;
        As[0][lk4 + 2][lrow] = a.z;  As[0][lk4 + 3][lrow] = a.w;
        Bs[0][lk4 + 0][lrow] = bq.x; Bs[0][lk4 + 1][lrow] = bq.y;
        Bs[0][lk4 + 2][lrow] = bq.z; Bs[0][lk4 + 3][lrow] = bq.w;
    }
    __syncthreads();

#pragma unroll 2
    for (int k0 = 0; k0 < 256; k0 += 8) {
        const int buf = (k0 >> 3) & 1;
        const bool more = (k0 + 8) < 256;
        float4 na, nb;
        if (more) {
            na = *reinterpret_cast<const float4*>(A + (m0 + lrow) * 256 + k0 + 8 + lk4);
            nb = *reinterpret_cast<const float4*>(B + (n0 + lrow) * 256 + k0 + 8 + lk4);
        }

#pragma unroll
        for (int k = 0; k < 8; ++k) {
            const float4 a0 = *reinterpret_cast<const float4*>(&As[buf][k][(ty << 3) + 0]);
            const float4 a1 = *reinterpret_cast<const float4*>(&As[buf][k][(ty << 3) + 4]);
            const float4 b0 = *reinterpret_cast<const float4*>(&Bs[buf][k][(tx << 3) + 0]);
            const float4 b1 = *reinterpret_cast<const float4*>(&Bs[buf][k][(tx << 3) + 4]);
            const float am[8] = {a0.x, a0.y, a0.z, a0.w, a1.x, a1.y, a1.z, a1.w};
            const float bn[8] = {b0.x, b0.y, b0.z, b0.w, b1.x, b1.y, b1.z, b1.w};
#pragma unroll
            for (int i = 0; i < 8; ++i)
#pragma unroll
                for (int j = 0; j < 8; ++j)
                    acc[i][j] += am[i] * bn[j];
        }

        if (more) {
            const int nbuf = buf ^ 1;
            As[nbuf][lk4 + 0][lrow] = na.x;  As[nbuf][lk4 + 1][lrow] = na.y;
            As[nbuf][lk4 + 2][lrow] = na.z;  As[nbuf][lk4 + 3][lrow] = na.w;
            Bs[nbuf][lk4 + 0][lrow] = nb.x;  Bs[nbuf][lk4 + 1][lrow] = nb.y;
            Bs[nbuf][lk4 + 2][lrow] = nb.z;  Bs[nbuf][lk4 + 3][lrow] = nb.w;
        }
        __syncthreads();
    }

#pragma unroll
    for (int i = 0; i < 8; ++i) {
        const int m = m0 + (ty << 3) + i;
#pragma unroll
        for (int j = 0; j < 8; ++j) {
            const int n = n0 + (tx << 3) + j;
            const float v = acc[i][j] + bias[bias_mode ? m : n];
            C[m * 256 + n] = fmaxf(v, 0.0f);
        }
    }
}

// GEMM1: h[b][n][d] = relu( sum_c pos[b][n][c] * W1[d][c] + b1[d] )
__global__ __launch_bounds__(256) void k_gemm1(const float* __restrict__ W1,
                                               const float* __restrict__ b1) {
    const float* A = g_pos + (long)blockIdx.z * NQ * DD;  // [n][c]
    float*       C = g_h   + (long)blockIdx.z * NQ * DD;  // [n][d]
    gemm_body(A, W1, b1, C, 0);
}

// GEMM2: out[b][d][n] = relu( sum_c W2[d][c] * h[b][n][c] + b2[d] )
__global__ __launch_bounds__(256) void k_gemm2(const float* __restrict__ W2,
                                               const float* __restrict__ b2,
                                               float* __restrict__ outp) {
    const float* B = g_h + (long)blockIdx.z * NQ * DD;    // [n][c]
    float*       C = outp + (long)blockIdx.z * DD * NQ;   // [d][n]
    gemm_body(W2, B, b2, C, 1);
}

// ---------------- launch ----------------
extern "C" void kernel_launch(void* const* d_in, const int* in_sizes, int n_in,
                              void* d_out, int out_size) {
    const float* xyz    = (const float*)d_in[0];
    const float* pc_min = (const float*)d_in[1];
    const float* pc_max = (const float*)d_in[2];
    const float* gB     = (const float*)d_in[3];
    const float* W1     = (const float*)d_in[4];
    const float* b1     = (const float*)d_in[5];
    const float* W2     = (const float*)d_in[6];
    const float* b2     = (const float*)d_in[7];
    float* out = (float*)d_out;

    k_transpose<<<(BATCH * NPTS / 4 + 255) / 256, 256>>>(xyz);
    k_fps<<<BATCH * CSZ, FPS_T>>>();
    k_embed<<<BATCH, NQ>>>(xyz, pc_min, pc_max, gB, out);
    dim3 gg(2, 2, BATCH);
    k_gemm1<<<gg, 256>>>(W1, b1);
    k_gemm2<<<gg, 256>>>(W2, b2, out + (long)BATCH * NQ * 3);
}